// round 8
// baseline (speedup 1.0000x reference)
#include <cuda_runtime.h>
#include <cstdint>

#define NB 32
#define LQ 18
#define LK 4096
#define DD 768
#define SCALE_F 0.03608439182435161f   // 1/sqrt(768)

#define T1   256
#define GRID 296              // 148 SMs * 2 CTAs, all resident (smem-guaranteed)
#define MT   128              // A job: k-rows
#define NMT  32               // A jobs per batch
#define CC   32
#define NCH  24
#define QSTR 1544
#define KSTR 72
#define KBUF 9216
#define TKB  256              // B job: k-rows
#define NBJ  16               // B jobs per batch
#define NJOB 1536             // 32*(32+16)

// smem layout (bytes) — R6 p1 layout + flags; B-job wl/sa alias A's K-tile scratch
#define SM_U8   0
#define SM_JOB  4
#define SM_BQ   8
#define SM_LAST 12
#define SM_RED  64            // 8 warps * 24 floats
#define SM_QHI  1024          // 27792
#define SM_QLO  28816         // 27792
#define SM_KHI  56704         // 9216 (single bf16 K tile buffer)
#define SM_KLO  65920         // 9216
#define SM_WL   (SM_KHI + 0)      // alias (B jobs only)
#define SM_SA   (SM_KHI + 128)    // alias, 1024B
#define SM_STG  75136         // 2 * 16384 fp32 staging
#define SMEM_BYTES 107904

// ---- device scratch (zero-init, self-cleaning) ----
__device__ float g_e[(size_t)NB*LQ*LK];
__device__ float g_lp[NB][NMT][LQ];
__device__ float g_cp[NB][NBJ][DD];
__device__ int   g_cntA[NB];
__device__ int   g_cntB[NB];
__device__ int   g_q;
__device__ int   g_done;

__device__ __forceinline__ uint32_t bfpack(float a, float b) {   // low16=bf16(a)
    uint32_t r;
    asm("cvt.rn.bf16x2.f32 %0, %1, %2;" : "=r"(r) : "f"(b), "f"(a));
    return r;
}
__device__ __forceinline__ float bflo_f(uint32_t h) { return __uint_as_float(h << 16); }
__device__ __forceinline__ float bfhi_f(uint32_t h) { return __uint_as_float(h & 0xffff0000u); }
__device__ __forceinline__ uint32_t smem_u32(const void* p) {
    uint32_t a;
    asm("{ .reg .u64 t; cvta.to.shared.u64 t, %1; cvt.u32.u64 %0, t; }" : "=r"(a) : "l"(p));
    return a;
}
#define CP_ASYNC16(dst, src) \
    asm volatile("cp.async.cg.shared.global [%0], [%1], 16;" :: "r"(dst), "l"(src) : "memory")
#define CP_COMMIT() asm volatile("cp.async.commit_group;" ::: "memory")
#define CP_WAIT1()  asm volatile("cp.async.wait_group 1;" ::: "memory")
#define CP_WAIT0()  asm volatile("cp.async.wait_group 0;" ::: "memory")
#define MMA(ac, a0,a1,a2,a3, b0,b1) \
    asm volatile("mma.sync.aligned.m16n8k16.row.col.f32.bf16.bf16.f32 " \
        "{%0,%1,%2,%3}, {%4,%5,%6,%7}, {%8,%9}, {%0,%1,%2,%3};" \
        : "+f"((ac)[0]),"+f"((ac)[1]),"+f"((ac)[2]),"+f"((ac)[3]) \
        : "r"(a0),"r"(a1),"r"(a2),"r"(a3),"r"(b0),"r"(b1))

__global__ __launch_bounds__(T1, 2) void fused(const float* __restrict__ Q,
                                               const float* __restrict__ K,
                                               const float* __restrict__ V,
                                               const void* __restrict__ Mv,
                                               const float* __restrict__ W,
                                               float* __restrict__ out) {
    extern __shared__ char smem[];
    const uint32_t sb = smem_u32(smem);
    const int tid = threadIdx.x, w = tid >> 5, lane = tid & 31;
    const int gid = lane >> 2, tig = lane & 3;

    if (tid == 0) { *(int*)(smem + SM_U8) = 0; *(int*)(smem + SM_BQ) = -1; }
    __syncthreads();
    // mask dtype probe: int32 0/1 has zero bytes at offsets %4!=0; u8 bool does not
    if (tid < 64) {
        uchar4 v = ((const uchar4*)Mv)[tid];
        if (v.y | v.z | v.w) atomicOr((int*)(smem + SM_U8), 1);
    }

    for (;;) {
        __syncthreads();                       // protect s_job + smem reuse across jobs
        if (tid == 0) *(volatile int*)(smem + SM_JOB) = atomicAdd(&g_q, 1);
        __syncthreads();
        const int j = *(volatile int*)(smem + SM_JOB);
        if (j >= NJOB) break;

        // decode queue: [A(b0)x32] then groups g=0..30: [A(g+1)x32, B(g)x16], then B(31)x16
        int isA, b, t;
        if (j < 32)        { isA = 1; b = 0; t = j; }
        else if (j < 1520) { int m = j - 32, g = m / 48, r = m % 48;
                             if (r < 32) { isA = 1; b = g + 1; t = r; }
                             else        { isA = 0; b = g;     t = r - 32; } }
        else               { isA = 0; b = 31; t = j - 1520; }

        if (isA) {
            // ============ A job: scores^T tile via split-bf16 mma.sync (R6 body) ============
            const int k0 = t * MT;
            const float* Kb = K + ((size_t)b * LK + k0) * DD;

            // stage chunk 0
#pragma unroll
            for (int i = 0; i < 4; i++) {
                int g = tid + i * 256, r = g >> 3, f = g & 7;
                CP_ASYNC16(sb + SM_STG + (uint32_t)(r * 8 + (f ^ (r & 7))) * 16,
                           Kb + (size_t)r * DD + f * 4);
            }
            CP_COMMIT();

            // Q -> bf16 hi/lo smem (cached per batch; B jobs never touch it)
            if (*(volatile int*)(smem + SM_BQ) != b) {
                const float4* Q4 = (const float4*)(Q + (size_t)b * LQ * DD);
                for (int idx = tid; idx < LQ * 192; idx += T1) {
                    int q = idx / 192, f = idx % 192;
                    float4 v = Q4[idx];
                    uint32_t h0 = bfpack(v.x, v.y), h1 = bfpack(v.z, v.w);
                    uint32_t l0 = bfpack(v.x - bflo_f(h0), v.y - bfhi_f(h0));
                    uint32_t l1 = bfpack(v.z - bflo_f(h1), v.w - bfhi_f(h1));
                    *(uint2*)(smem + SM_QHI + q * QSTR + f * 8) = make_uint2(h0, h1);
                    *(uint2*)(smem + SM_QLO + q * QSTR + f * 8) = make_uint2(l0, l1);
                }
                if (tid == 0) *(volatile int*)(smem + SM_BQ) = b;
            }

            float acc[3][4];
#pragma unroll
            for (int nt = 0; nt < 3; nt++)
#pragma unroll
                for (int i = 0; i < 4; i++) acc[nt][i] = 0.f;

            const int M0 = w * 16;
            const int cr = tid >> 1, chalf = tid & 1;

            for (int c = 0; c < NCH; c++) {
                if (c + 1 < NCH) {
                    const float* src = Kb + (c + 1) * CC;
                    uint32_t base = sb + SM_STG + ((c + 1) & 1) * 16384;
#pragma unroll
                    for (int i = 0; i < 4; i++) {
                        int g = tid + i * 256, r = g >> 3, f = g & 7;
                        CP_ASYNC16(base + (uint32_t)(r * 8 + (f ^ (r & 7))) * 16,
                                   src + (size_t)r * DD + f * 4);
                    }
                    CP_COMMIT();
                    CP_WAIT1();
                } else {
                    CP_WAIT0();
                }
                __syncthreads();           // chunk c staged; prev MMA reads done

                {   // convert chunk c fp32 -> bf16 hi/lo tiles
                    const char* sbuf = smem + SM_STG + (c & 1) * 16384;
#pragma unroll
                    for (int jj = 0; jj < 4; jj++) {
                        int f = chalf * 4 + jj;
                        float4 v = *(const float4*)(sbuf + (cr * 8 + (f ^ (cr & 7))) * 16);
                        uint32_t h0 = bfpack(v.x, v.y), h1 = bfpack(v.z, v.w);
                        uint32_t l0 = bfpack(v.x - bflo_f(h0), v.y - bfhi_f(h0));
                        uint32_t l1 = bfpack(v.z - bflo_f(h1), v.w - bfhi_f(h1));
                        *(uint2*)(smem + SM_KHI + cr * KSTR + f * 8) = make_uint2(h0, h1);
                        *(uint2*)(smem + SM_KLO + cr * KSTR + f * 8) = make_uint2(l0, l1);
                    }
                }
                __syncthreads();

#pragma unroll
                for (int s = 0; s < 2; s++) {
                    const int kc = s * 16;
                    const char* ka = smem + SM_KHI + (M0 + gid) * KSTR + (kc + tig * 2) * 2;
                    const char* la = smem + SM_KLO + (M0 + gid) * KSTR + (kc + tig * 2) * 2;
                    uint32_t ah0 = *(const uint32_t*)ka;
                    uint32_t ah1 = *(const uint32_t*)(ka + 8 * KSTR);
                    uint32_t ah2 = *(const uint32_t*)(ka + 16);
                    uint32_t ah3 = *(const uint32_t*)(ka + 8 * KSTR + 16);
                    uint32_t al0 = *(const uint32_t*)la;
                    uint32_t al1 = *(const uint32_t*)(la + 8 * KSTR);
                    uint32_t al2 = *(const uint32_t*)(la + 16);
                    uint32_t al3 = *(const uint32_t*)(la + 8 * KSTR + 16);
                    const int dglob = c * CC + kc + tig * 2;
#pragma unroll
                    for (int nt = 0; nt < 3; nt++) {
                        int q = nt * 8 + gid; if (q > 17) q = 17;
                        const char* qh = smem + SM_QHI + q * QSTR + dglob * 2;
                        const char* ql = smem + SM_QLO + q * QSTR + dglob * 2;
                        uint32_t bh0 = *(const uint32_t*)qh;
                        uint32_t bh1 = *(const uint32_t*)(qh + 16);
                        uint32_t bl0 = *(const uint32_t*)ql;
                        uint32_t bl1 = *(const uint32_t*)(ql + 16);
                        MMA(acc[nt], ah0, ah1, ah2, ah3, bh0, bh1);
                        MMA(acc[nt], ah0, ah1, ah2, ah3, bl0, bl1);
                        MMA(acc[nt], al0, al1, al2, al3, bh0, bh1);
                    }
                }
            }

            // epilogue: mask + exp + g_e + per-q row sums
            const int u8 = *(volatile int*)(smem + SM_U8);
            const unsigned char* M8  = (const unsigned char*)Mv;
            const int*           M32 = (const int*)Mv;
            float* red = (float*)(smem + SM_RED);
            const int ra = M0 + gid, rb = ra + 8;
#pragma unroll
            for (int nt = 0; nt < 3; nt++) {
                const int q0 = nt * 8 + tig * 2, q1 = q0 + 1;
                float e0 = 0.f, e1 = 0.f, e2 = 0.f, e3 = 0.f;
                if (q0 < LQ) {
                    size_t o = ((size_t)b * LQ + q0) * LK + k0;
                    int m0 = u8 ? (int)M8[o + ra] : M32[o + ra];
                    int m2 = u8 ? (int)M8[o + rb] : M32[o + rb];
                    e0 = m0 ? 0.f : __expf(acc[nt][0] * SCALE_F);
                    e2 = m2 ? 0.f : __expf(acc[nt][2] * SCALE_F);
                    g_e[o + ra] = e0;
                    g_e[o + rb] = e2;
                }
                if (q1 < LQ) {
                    size_t o = ((size_t)b * LQ + q1) * LK + k0;
                    int m1 = u8 ? (int)M8[o + ra] : M32[o + ra];
                    int m3 = u8 ? (int)M8[o + rb] : M32[o + rb];
                    e1 = m1 ? 0.f : __expf(acc[nt][1] * SCALE_F);
                    e3 = m3 ? 0.f : __expf(acc[nt][3] * SCALE_F);
                    g_e[o + ra] = e1;
                    g_e[o + rb] = e3;
                }
                float s0 = e0 + e2, s1 = e1 + e3;
#pragma unroll
                for (int m = 4; m <= 16; m <<= 1) {
                    s0 += __shfl_xor_sync(0xffffffffu, s0, m);
                    s1 += __shfl_xor_sync(0xffffffffu, s1, m);
                }
                if (gid == 0) {
                    if (q0 < LQ) red[w * 24 + q0] = s0;
                    if (q1 < LQ) red[w * 24 + q1] = s1;
                }
            }
            __syncthreads();
            if (tid < LQ) {
                float l = 0.f;
#pragma unroll
                for (int ww = 0; ww < 8; ww++) l += red[ww * 24 + tid];
                g_lp[b][t][tid] = l;
            }
            __syncthreads();
            if (tid == 0) { __threadfence(); atomicAdd(&g_cntA[b], 1); }  // release gate
        } else {
            // ============ B job: attn_fc + context partial (p2 body) ============
            const int k0 = t * TKB;
            float* wl = (float*)(smem + SM_WL);
            float* sa = (float*)(smem + SM_SA);

            if (tid == 0) {                    // gate: batch b fully scored
                while (atomicAdd(&g_cntA[b], 0) < NMT) __nanosleep(200);
                __threadfence();
            }
            __syncthreads();

            if (tid < LQ) {
                float l = 0.f;
#pragma unroll
                for (int tt = 0; tt < NMT; tt++) l += g_lp[b][tt][tid];
                wl[tid] = W[tid] / l;
            }
            __syncthreads();

            {   // attn_fc: one k per thread
                const int k = k0 + tid;
                float a = 0.f;
#pragma unroll
                for (int q = 0; q < LQ; q++)
                    a = fmaf(g_e[((size_t)b * LQ + q) * LK + k], wl[q], a);
                out[(size_t)NB * DD + (size_t)b * LK + k] = a;
                sa[tid] = a;
            }
            __syncthreads();

            if (tid < DD / 4) {                // context partial: float4 column per thread
                const float4* V4 = (const float4*)(V + ((size_t)b * LK + k0) * DD);
                float cx = 0.f, cy = 0.f, cz = 0.f, cw = 0.f;
#pragma unroll 16
                for (int kk = 0; kk < TKB; kk++) {
                    float  av = sa[kk];
                    float4 v  = V4[(size_t)kk * (DD / 4) + tid];
                    cx = fmaf(av, v.x, cx);
                    cy = fmaf(av, v.y, cy);
                    cz = fmaf(av, v.z, cz);
                    cw = fmaf(av, v.w, cw);
                }
                ((float4*)g_cp[b][t])[tid] = make_float4(cx, cy, cz, cw);
            }
            __syncthreads();
            if (tid == 0) {
                __threadfence();
                *(volatile int*)(smem + SM_LAST) = (atomicAdd(&g_cntB[b], 1) == NBJ - 1);
            }
            __syncthreads();
            if (*(volatile int*)(smem + SM_LAST)) {
                if (tid < DD / 4) {            // fixed-order deterministic reduction
                    float4 a = make_float4(0.f, 0.f, 0.f, 0.f);
#pragma unroll
                    for (int tt = 0; tt < NBJ; tt++) {
                        float4 v = ((const float4*)g_cp[b][tt])[tid];
                        a.x += v.x; a.y += v.y; a.z += v.z; a.w += v.w;
                    }
                    ((float4*)(out + (size_t)b * DD))[tid] = a;
                }
                if (tid == 0) { g_cntA[b] = 0; g_cntB[b] = 0; }   // self-clean
            }
        }
    }

    // last CTA out resets the queue for the next graph replay
    if (tid == 0) {
        if (atomicAdd(&g_done, 1) == GRID - 1) { g_q = 0; g_done = 0; }
    }
}

extern "C" void kernel_launch(void* const* d_in, const int* in_sizes, int n_in,
                              void* d_out, int out_size) {
    const float* Q = (const float*)d_in[0];
    const float* K = (const float*)d_in[1];
    const float* V = (const float*)d_in[2];
    const void*  M = d_in[3];
    const float* W = (const float*)d_in[4];
    float* out = (float*)d_out;

    cudaFuncSetAttribute(fused, cudaFuncAttributeMaxDynamicSharedMemorySize, SMEM_BYTES);
    fused<<<GRID, T1, SMEM_BYTES>>>(Q, K, V, M, W, out);
}

// round 9
// speedup vs baseline: 1.1918x; 1.1918x over previous
#include <cuda_runtime.h>
#include <cstdint>

#define NB 32
#define LQ 18
#define LK 4096
#define DD 768
#define SCALE_F 0.03608439182435161f   // 1/sqrt(768)

// ---- p1 config ----
#define T1   256
#define MT   128             // k-rows per CTA
#define NMT  (LK/MT)         // 32
#define CC   32              // K cols per chunk
#define NCH  (DD/CC)         // 24
#define QSTR 1544            // Q row stride bytes (768*2 + 8 pad)
#define KSTR 72              // K tile row stride bytes
#define KBUF 9216            // one bf16 K tile buffer (128*72)
#define WSTG 4096            // per-warp staging (2 bufs x 2048)

// smem layout (bytes)
#define SM_U8   0
#define SM_RED  64           // 8 warps * 24 floats
#define SM_QHI  1024         // 27792
#define SM_QLO  28816        // 27792
#define SM_KHI  56640        // 2 bufs
#define SM_KLO  (SM_KHI + 2*KBUF)        // 75072, 2 bufs
#define SM_STG  (SM_KLO + 2*KBUF + 64)   // 93568; 8 warps * 4096
#define SMEM1_BYTES (SM_STG + 8*WSTG)    // 126336? (128*256=32768) -> 126336
// 126336 > 113.5K would kill 2 CTA/SM; shrink: KHI/KLO single... no — check:
// 93568 + 32768 = 126336. Too big. Fix: per-warp staging aliases nothing else;
// reduce by overlapping staging with nothing... instead drop KLO second buffer?
// Cleaner: KHI/KLO need only SINGLE buffer now? MMA c reads kbuf, convert c+1
// writes other parity. Keep 2 bufs but shrink staging: stg buf = 2048/warp/buf
// is minimal. Alternative: reuse the 16KB gap by overlapping SM_STG into the
// second KLO buffer? No. Use KSTR=68 (32*2+4): rows 128*68=8704/buf.
// Recompute tight: QHI 27792 QLO 27792 KHI 2*8704=17408 KLO 17408 STG 32768
// + 1024 head = 124192. Still >113.5K. Drop to 1 CTA/SM? No.
// Solution: single kbuf parity is NOT safe, but staging CAN overlap KLO buf1
// if we use single-buffer kbuf with extra syncwarp? Simplest: CC=16 chunks=48,
// stg/warp/buf = 1024B -> STG 16384. KSTR for 16 cols = 40B, KBUF=5120.
// QHI 27792 + QLO 27792 + 2*5120 + 2*5120 + 16384 + 1024 = 93472. Fits!
#undef CC
#undef NCH
#undef KSTR
#undef KBUF
#undef WSTG
#undef SM_KHI
#undef SM_KLO
#undef SM_STG
#undef SMEM1_BYTES
#define CC   16
#define NCH  (DD/CC)         // 48
#define KSTR 40              // 16*2 + 8 pad
#define KBUF 5120            // 128*40
#define WSTG 2048            // per-warp staging: 2 bufs x 1024 (16 rows x 64B)
#define SM_KHI 56640
#define SM_KLO (SM_KHI + 2*KBUF)         // 66880
#define SM_STG (SM_KLO + 2*KBUF + 64)    // 77184
#define SMEM1_BYTES (SM_STG + 8*WSTG)    // 93568

// ---- p2 config (at HBM roofline, unchanged) ----
#define TK2 256
#define NT2 (LK/TK2)
#define T2  192

// ---- device scratch ----
__device__ float g_e[(size_t)NB*LQ*LK];
__device__ float g_lp[NB][NMT][LQ];
__device__ float g_cp[NB][NT2][DD];
__device__ int   g_cnt[NB];

__device__ __forceinline__ uint32_t bfpack(float a, float b) {   // low16=bf16(a)
    uint32_t r;
    asm("cvt.rn.bf16x2.f32 %0, %1, %2;" : "=r"(r) : "f"(b), "f"(a));
    return r;
}
__device__ __forceinline__ float bflo_f(uint32_t h) { return __uint_as_float(h << 16); }
__device__ __forceinline__ float bfhi_f(uint32_t h) { return __uint_as_float(h & 0xffff0000u); }
__device__ __forceinline__ uint32_t smem_u32(const void* p) {
    uint32_t a;
    asm("{ .reg .u64 t; cvta.to.shared.u64 t, %1; cvt.u32.u64 %0, t; }" : "=r"(a) : "l"(p));
    return a;
}
#define CP_ASYNC16(dst, src) \
    asm volatile("cp.async.cg.shared.global [%0], [%1], 16;" :: "r"(dst), "l"(src) : "memory")
#define CP_COMMIT() asm volatile("cp.async.commit_group;" ::: "memory")
#define CP_WAIT1()  asm volatile("cp.async.wait_group 1;" ::: "memory")
#define CP_WAIT0()  asm volatile("cp.async.wait_group 0;" ::: "memory")
#define MMA(ac, a0,a1,a2,a3, b0,b1) \
    asm volatile("mma.sync.aligned.m16n8k16.row.col.f32.bf16.bf16.f32 " \
        "{%0,%1,%2,%3}, {%4,%5,%6,%7}, {%8,%9}, {%0,%1,%2,%3};" \
        : "+f"((ac)[0]),"+f"((ac)[1]),"+f"((ac)[2]),"+f"((ac)[3]) \
        : "r"(a0),"r"(a1),"r"(a2),"r"(a3),"r"(b0),"r"(b1))

// ---------------- p1: warp-autonomous split-bf16 mma.sync pipeline ----------------
__global__ __launch_bounds__(T1, 2) void p1(const float* __restrict__ Q,
                                            const float* __restrict__ K,
                                            const void* __restrict__ Mv) {
    extern __shared__ char smem[];
    const uint32_t sb = smem_u32(smem);
    const int tid = threadIdx.x, w = tid >> 5, lane = tid & 31;
    const int gid = lane >> 2, tig = lane & 3;
    const int b = blockIdx.y, mt = blockIdx.x, k0 = mt * MT;
    const int M0 = w * 16;

    if (tid == 0) *(int*)(smem + SM_U8) = 0;
    __syncthreads();
    // mask dtype probe: int32 0/1 has zero bytes at offsets %4!=0; u8 bool does not
    if (tid < 64) {
        uchar4 v = ((const uchar4*)Mv)[tid];
        if (v.y | v.z | v.w) atomicOr((int*)(smem + SM_U8), 1);
    }

    // per-warp staging: 16 rows x 16 floats per chunk, xor-swizzled float4s
    // cp.async: lane covers 2 float4 (g = i*32+lane, i=0..1; r=g>>2, f=g&3)
    const uint32_t stg = sb + SM_STG + w * WSTG;
    const float* Kw = K + ((size_t)b * LK + k0 + M0) * DD;     // warp's 16 rows
    {
#pragma unroll
        for (int i = 0; i < 2; i++) {
            int g = i * 32 + lane, r = g >> 2, f = g & 3;
            CP_ASYNC16(stg + (uint32_t)(r * 4 + (f ^ (r & 3))) * 16,
                       Kw + (size_t)r * DD + f * 4);
        }
        CP_COMMIT();
    }

    // Q -> bf16 hi/lo smem (whole CTA, once)
    {
        const float4* Q4 = (const float4*)(Q + (size_t)b * LQ * DD);
        for (int idx = tid; idx < LQ * 192; idx += T1) {
            int q = idx / 192, f = idx % 192;
            float4 v = Q4[idx];
            uint32_t h0 = bfpack(v.x, v.y), h1 = bfpack(v.z, v.w);
            uint32_t l0 = bfpack(v.x - bflo_f(h0), v.y - bfhi_f(h0));
            uint32_t l1 = bfpack(v.z - bflo_f(h1), v.w - bfhi_f(h1));
            *(uint2*)(smem + SM_QHI + q * QSTR + f * 8) = make_uint2(h0, h1);
            *(uint2*)(smem + SM_QLO + q * QSTR + f * 8) = make_uint2(l0, l1);
        }
    }
    __syncthreads();   // Q visible to all warps; main loop is barrier-free

    float acc[3][4];
#pragma unroll
    for (int nt = 0; nt < 3; nt++)
#pragma unroll
        for (int i = 0; i < 4; i++) acc[nt][i] = 0.f;

    // convert roles: lane owns row lane>>1, half lane&1 (8 floats = 2 float4)
    const int crow = lane >> 1, chalf = lane & 1;

    for (int c = 0; c < NCH; c++) {
        if (c + 1 < NCH) {   // per-warp prefetch chunk c+1
            const uint32_t dst = stg + ((c + 1) & 1) * 1024;
            const float* src = Kw + (c + 1) * CC;
#pragma unroll
            for (int i = 0; i < 2; i++) {
                int g = i * 32 + lane, r = g >> 2, f = g & 3;
                CP_ASYNC16(dst + (uint32_t)(r * 4 + (f ^ (r & 3))) * 16,
                           src + (size_t)r * DD + f * 4);
            }
            CP_COMMIT();
            CP_WAIT1();
        } else {
            CP_WAIT0();
        }
        __syncwarp();

        // convert chunk c -> warp's kbuf rows (buffer c&1)
        {
            const char* sbuf = smem + (stg - sb) + (c & 1) * 1024;
            const uint32_t kb = (uint32_t)((c & 1) * KBUF) + (M0 + crow) * KSTR + chalf * 16;
#pragma unroll
            for (int j = 0; j < 2; j++) {
                int f = chalf * 2 + j;
                float4 v = *(const float4*)(sbuf + (crow * 4 + (f ^ (crow & 3))) * 16);
                uint32_t h0 = bfpack(v.x, v.y), h1 = bfpack(v.z, v.w);
                uint32_t l0 = bfpack(v.x - bflo_f(h0), v.y - bfhi_f(h0));
                uint32_t l1 = bfpack(v.z - bflo_f(h1), v.w - bfhi_f(h1));
                *(uint2*)(smem + SM_KHI + kb + j * 8) = make_uint2(h0, h1);
                *(uint2*)(smem + SM_KLO + kb + j * 8) = make_uint2(l0, l1);
            }
        }
        __syncwarp();

        // one k16 MMA step per 16-col chunk
        {
            const int base = (c & 1) * KBUF;
            const char* ka = smem + SM_KHI + base + (M0 + gid) * KSTR + tig * 4;
            const char* la = smem + SM_KLO + base + (M0 + gid) * KSTR + tig * 4;
            uint32_t ah0 = *(const uint32_t*)ka;
            uint32_t ah1 = *(const uint32_t*)(ka + 8 * KSTR);
            uint32_t ah2 = *(const uint32_t*)(ka + 16);
            uint32_t ah3 = *(const uint32_t*)(ka + 8 * KSTR + 16);
            uint32_t al0 = *(const uint32_t*)la;
            uint32_t al1 = *(const uint32_t*)(la + 8 * KSTR);
            uint32_t al2 = *(const uint32_t*)(la + 16);
            uint32_t al3 = *(const uint32_t*)(la + 8 * KSTR + 16);
            const int dglob = c * CC + tig * 2;
#pragma unroll
            for (int nt = 0; nt < 3; nt++) {
                int q = nt * 8 + gid; if (q > 17) q = 17;   // clamp pad rows
                const char* qh = smem + SM_QHI + q * QSTR + dglob * 2;
                const char* ql = smem + SM_QLO + q * QSTR + dglob * 2;
                uint32_t bh0 = *(const uint32_t*)qh;
                uint32_t bh1 = *(const uint32_t*)(qh + 16);
                uint32_t bl0 = *(const uint32_t*)ql;
                uint32_t bl1 = *(const uint32_t*)(ql + 16);
                MMA(acc[nt], ah0, ah1, ah2, ah3, bh0, bh1);
                MMA(acc[nt], ah0, ah1, ah2, ah3, bl0, bl1);
                MMA(acc[nt], al0, al1, al2, al3, bh0, bh1);
            }
        }
    }

    // epilogue: mask + exp + g_e store + per-q row sums
    const int u8 = *(volatile int*)(smem + SM_U8);
    const unsigned char* M8  = (const unsigned char*)Mv;
    const int*           M32 = (const int*)Mv;
    float* red = (float*)(smem + SM_RED);
    const int ra = M0 + gid, rb = ra + 8;
#pragma unroll
    for (int nt = 0; nt < 3; nt++) {
        const int q0 = nt * 8 + tig * 2, q1 = q0 + 1;
        float e0 = 0.f, e1 = 0.f, e2 = 0.f, e3 = 0.f;
        if (q0 < LQ) {
            size_t o = ((size_t)b * LQ + q0) * LK + k0;
            int m0 = u8 ? (int)M8[o + ra] : M32[o + ra];
            int m2 = u8 ? (int)M8[o + rb] : M32[o + rb];
            e0 = m0 ? 0.f : __expf(acc[nt][0] * SCALE_F);
            e2 = m2 ? 0.f : __expf(acc[nt][2] * SCALE_F);
            g_e[o + ra] = e0;
            g_e[o + rb] = e2;
        }
        if (q1 < LQ) {
            size_t o = ((size_t)b * LQ + q1) * LK + k0;
            int m1 = u8 ? (int)M8[o + ra] : M32[o + ra];
            int m3 = u8 ? (int)M8[o + rb] : M32[o + rb];
            e1 = m1 ? 0.f : __expf(acc[nt][1] * SCALE_F);
            e3 = m3 ? 0.f : __expf(acc[nt][3] * SCALE_F);
            g_e[o + ra] = e1;
            g_e[o + rb] = e3;
        }
        float s0 = e0 + e2, s1 = e1 + e3;
#pragma unroll
        for (int m = 4; m <= 16; m <<= 1) {
            s0 += __shfl_xor_sync(0xffffffffu, s0, m);
            s1 += __shfl_xor_sync(0xffffffffu, s1, m);
        }
        if (gid == 0) {
            if (q0 < LQ) red[w * 24 + q0] = s0;
            if (q1 < LQ) red[w * 24 + q1] = s1;
        }
    }
    __syncthreads();
    if (tid < LQ) {
        float l = 0.f;
#pragma unroll
        for (int ww = 0; ww < 8; ww++) l += red[ww * 24 + tid];
        g_lp[b][mt][tid] = l;
    }
}

// ---------------- p2: attn_fc + context (unchanged; at HBM roofline) ----------------
__global__ __launch_bounds__(T2) void p2(const float* __restrict__ V,
                                         const float* __restrict__ W,
                                         float* __restrict__ out) {
    __shared__ float wl[LQ];
    __shared__ float sa[TK2];
    __shared__ int s_last;
    const int tid  = threadIdx.x;
    const int b    = blockIdx.y;
    const int tile = blockIdx.x;
    const int k0   = tile * TK2;

    if (tid < LQ) {
        float l = 0.f;
#pragma unroll
        for (int t = 0; t < NMT; t++) l += g_lp[b][t][tid];
        wl[tid] = W[tid] / l;
    }
    __syncthreads();

    for (int kk = tid; kk < TK2; kk += T2) {
        const int k = k0 + kk;
        float a = 0.f;
#pragma unroll
        for (int q = 0; q < LQ; q++)
            a = fmaf(g_e[((size_t)b*LQ + q)*LK + k], wl[q], a);
        out[(size_t)NB*DD + (size_t)b*LK + k] = a;
        sa[kk] = a;
    }
    __syncthreads();

    const float4* V4 = (const float4*)(V + ((size_t)b*LK + k0)*DD);
    float cx = 0.f, cy = 0.f, cz = 0.f, cw = 0.f;
#pragma unroll 8
    for (int kk = 0; kk < TK2; kk++) {
        float  av = sa[kk];
        float4 v  = V4[(size_t)kk*(DD/4) + tid];
        cx = fmaf(av, v.x, cx);
        cy = fmaf(av, v.y, cy);
        cz = fmaf(av, v.z, cz);
        cw = fmaf(av, v.w, cw);
    }
    ((float4*)g_cp[b][tile])[tid] = make_float4(cx, cy, cz, cw);
    __threadfence();
    __syncthreads();
    if (tid == 0) s_last = (atomicAdd(&g_cnt[b], 1) == NT2 - 1);
    __syncthreads();
    if (s_last) {
        float4 a = make_float4(0.f, 0.f, 0.f, 0.f);
#pragma unroll
        for (int t = 0; t < NT2; t++) {
            float4 v = ((const float4*)g_cp[b][t])[tid];
            a.x += v.x; a.y += v.y; a.z += v.z; a.w += v.w;
        }
        ((float4*)(out + (size_t)b*DD))[tid] = a;
        if (tid == 0) g_cnt[b] = 0;
    }
}

extern "C" void kernel_launch(void* const* d_in, const int* in_sizes, int n_in,
                              void* d_out, int out_size) {
    const float* Q = (const float*)d_in[0];
    const float* K = (const float*)d_in[1];
    const float* V = (const float*)d_in[2];
    const void*  M = d_in[3];
    const float* W = (const float*)d_in[4];
    float* out = (float*)d_out;

    cudaFuncSetAttribute(p1, cudaFuncAttributeMaxDynamicSharedMemorySize, SMEM1_BYTES);

    p1<<<dim3(NMT, NB), T1, SMEM1_BYTES>>>(Q, K, M);
    p2<<<dim3(NT2, NB), T2>>>(V, W, out);
}

// round 10
// speedup vs baseline: 1.4636x; 1.2281x over previous
#include <cuda_runtime.h>
#include <cstdint>

#define NB 32
#define LQ 18
#define LK 4096
#define DD 768
#define SCALE_F 0.03608439182435161f   // 1/sqrt(768)

// ---- p1 config ----
#define T1   256
#define MT   128             // k-rows per CTA
#define NMT  (LK/MT)         // 32
#define CC   16              // K cols per chunk
#define NCH  (DD/CC)         // 48
#define QSTR 1544            // Q row stride bytes (768*2 + 8 pad)
#define WSTG 4096            // per-warp staging: 4 bufs x 1024B (16 rows x 64B)

// smem layout (bytes)
#define SM_U8   0
#define SM_RED  64           // 8 warps * 24 floats
#define SM_QHI  1024         // 27792
#define SM_QLO  28816        // 27792 -> ends 56608
#define SM_STG  56640        // 8 warps * 4096
#define SMEM1_BYTES (SM_STG + 8*WSTG)   // 89408

// ---- p2 config (at HBM roofline, unchanged) ----
#define TK2 256
#define NT2 (LK/TK2)
#define T2  192

// ---- device scratch ----
__device__ float g_e[(size_t)NB*LQ*LK];
__device__ float g_lp[NB][NMT][LQ];
__device__ float g_cp[NB][NT2][DD];
__device__ int   g_cnt[NB];

__device__ __forceinline__ uint32_t bfpack(float a, float b) {   // low16=bf16(a)
    uint32_t r;
    asm("cvt.rn.bf16x2.f32 %0, %1, %2;" : "=r"(r) : "f"(b), "f"(a));
    return r;
}
__device__ __forceinline__ float bflo_f(uint32_t h) { return __uint_as_float(h << 16); }
__device__ __forceinline__ float bfhi_f(uint32_t h) { return __uint_as_float(h & 0xffff0000u); }
__device__ __forceinline__ uint32_t smem_u32(const void* p) {
    uint32_t a;
    asm("{ .reg .u64 t; cvta.to.shared.u64 t, %1; cvt.u32.u64 %0, t; }" : "=r"(a) : "l"(p));
    return a;
}
#define CP_ASYNC16(dst, src) \
    asm volatile("cp.async.cg.shared.global [%0], [%1], 16;" :: "r"(dst), "l"(src) : "memory")
#define CP_COMMIT() asm volatile("cp.async.commit_group;" ::: "memory")
#define CP_WAITN(n) asm volatile("cp.async.wait_group %0;" :: "n"(n) : "memory")
#define MMA(ac, a0,a1,a2,a3, b0,b1) \
    asm volatile("mma.sync.aligned.m16n8k16.row.col.f32.bf16.bf16.f32 " \
        "{%0,%1,%2,%3}, {%4,%5,%6,%7}, {%8,%9}, {%0,%1,%2,%3};" \
        : "+f"((ac)[0]),"+f"((ac)[1]),"+f"((ac)[2]),"+f"((ac)[3]) \
        : "r"(a0),"r"(a1),"r"(a2),"r"(a3),"r"(b0),"r"(b1))

// split one f32 pair into packed bf16x2 hi + lo
__device__ __forceinline__ void bfsplit(float2 v, uint32_t& h, uint32_t& l) {
    h = bfpack(v.x, v.y);
    l = bfpack(v.x - bflo_f(h), v.y - bfhi_f(h));
}

// ---------------- p1: warp-autonomous, register-fragment split-bf16 mma.sync ----------------
__global__ __launch_bounds__(T1, 2) void p1(const float* __restrict__ Q,
                                            const float* __restrict__ K,
                                            const void* __restrict__ Mv) {
    extern __shared__ char smem[];
    const uint32_t sb = smem_u32(smem);
    const int tid = threadIdx.x, w = tid >> 5, lane = tid & 31;
    const int gid = lane >> 2, tig = lane & 3;
    const int b = blockIdx.y, mt = blockIdx.x, k0 = mt * MT;
    const int M0 = w * 16;

    if (tid == 0) *(int*)(smem + SM_U8) = 0;
    __syncthreads();
    // mask dtype probe: int32 0/1 has zero bytes at offsets %4!=0; u8 bool does not
    if (tid < 64) {
        uchar4 v = ((const uchar4*)Mv)[tid];
        if (v.y | v.z | v.w) atomicOr((int*)(smem + SM_U8), 1);
    }

    // per-warp staging: chunk = 16 rows x 16 f32 (64B/row), xor-swizzled float4s
    const uint32_t stg = sb + SM_STG + w * WSTG;
    const float* Kw = K + ((size_t)b * LK + k0 + M0) * DD;     // warp's 16 rows

    // issue chunks 0..2 (pipeline depth 4: one group per chunk)
#pragma unroll
    for (int cc = 0; cc < 3; cc++) {
        const uint32_t dst = stg + (cc & 3) * 1024;
        const float* src = Kw + cc * CC;
#pragma unroll
        for (int i = 0; i < 2; i++) {
            int g = i * 32 + lane, r = g >> 2, f = g & 3;
            CP_ASYNC16(dst + (uint32_t)(r * 4 + (f ^ (r & 3))) * 16,
                       src + (size_t)r * DD + f * 4);
        }
        CP_COMMIT();
    }

    // Q -> bf16 hi/lo smem (whole CTA, once)
    {
        const float4* Q4 = (const float4*)(Q + (size_t)b * LQ * DD);
        for (int idx = tid; idx < LQ * 192; idx += T1) {
            int q = idx / 192, f = idx % 192;
            float4 v = Q4[idx];
            uint32_t h0 = bfpack(v.x, v.y), h1 = bfpack(v.z, v.w);
            uint32_t l0 = bfpack(v.x - bflo_f(h0), v.y - bfhi_f(h0));
            uint32_t l1 = bfpack(v.z - bflo_f(h1), v.w - bfhi_f(h1));
            *(uint2*)(smem + SM_QHI + q * QSTR + f * 8) = make_uint2(h0, h1);
            *(uint2*)(smem + SM_QLO + q * QSTR + f * 8) = make_uint2(l0, l1);
        }
    }
    __syncthreads();   // Q visible; main loop has NO syncs at all

    float acc[3][4];
#pragma unroll
    for (int nt = 0; nt < 3; nt++)
#pragma unroll
        for (int i = 0; i < 4; i++) acc[nt][i] = 0.f;

    // fragment addresses in staging (per chunk buffer):
    //  a0: row gid,   f32 cols 2tig..2tig+1  -> float4 f = tig>>1, half tig&1
    //  a1: row gid+8, same cols
    //  a2: row gid,   cols 2tig+8..9         -> f+2
    //  a3: row gid+8, f+2
    const int fA = tig >> 1, hA = tig & 1;
    const uint32_t oa0 = (uint32_t)((gid * 4 + (fA ^ (gid & 3))) * 16 + hA * 8);
    const uint32_t oa1 = (uint32_t)(((gid + 8) * 4 + (fA ^ ((gid + 8) & 3))) * 16 + hA * 8);
    const uint32_t oa2 = (uint32_t)((gid * 4 + ((fA + 2) ^ (gid & 3))) * 16 + hA * 8);
    const uint32_t oa3 = (uint32_t)(((gid + 8) * 4 + ((fA + 2) ^ ((gid + 8) & 3))) * 16 + hA * 8);

    for (int c = 0; c < NCH; c++) {
        // issue chunk c+3, then wait for chunk c
        if (c + 3 < NCH) {
            const uint32_t dst = stg + ((c + 3) & 3) * 1024;
            const float* src = Kw + (c + 3) * CC;
#pragma unroll
            for (int i = 0; i < 2; i++) {
                int g = i * 32 + lane, r = g >> 2, f = g & 3;
                CP_ASYNC16(dst + (uint32_t)(r * 4 + (f ^ (r & 3))) * 16,
                           src + (size_t)r * DD + f * 4);
            }
            CP_COMMIT();
            CP_WAITN(3);
        } else {
            int rem = NCH - 1 - c;
            if (rem == 2)      CP_WAITN(2);
            else if (rem == 1) CP_WAITN(1);
            else               CP_WAITN(0);
        }

        // load + split A fragments straight from staging (registers only)
        const char* buf = smem + (stg - sb) + (c & 3) * 1024;
        uint32_t ah0, ah1, ah2, ah3, al0, al1, al2, al3;
        bfsplit(*(const float2*)(buf + oa0), ah0, al0);
        bfsplit(*(const float2*)(buf + oa1), ah1, al1);
        bfsplit(*(const float2*)(buf + oa2), ah2, al2);
        bfsplit(*(const float2*)(buf + oa3), ah3, al3);

        const int dglob = c * CC + tig * 2;
#pragma unroll
        for (int nt = 0; nt < 3; nt++) {
            int q = nt * 8 + gid; if (q > 17) q = 17;   // clamp pad rows
            const char* qh = smem + SM_QHI + q * QSTR + dglob * 2;
            const char* ql = smem + SM_QLO + q * QSTR + dglob * 2;
            uint32_t bh0 = *(const uint32_t*)qh;
            uint32_t bh1 = *(const uint32_t*)(qh + 16);
            uint32_t bl0 = *(const uint32_t*)ql;
            uint32_t bl1 = *(const uint32_t*)(ql + 16);
            MMA(acc[nt], ah0, ah1, ah2, ah3, bh0, bh1);
            MMA(acc[nt], ah0, ah1, ah2, ah3, bl0, bl1);
            MMA(acc[nt], al0, al1, al2, al3, bh0, bh1);
        }
    }

    // epilogue: mask + exp + g_e store + per-q row sums
    const int u8 = *(volatile int*)(smem + SM_U8);
    const unsigned char* M8  = (const unsigned char*)Mv;
    const int*           M32 = (const int*)Mv;
    float* red = (float*)(smem + SM_RED);
    const int ra = M0 + gid, rb = ra + 8;
#pragma unroll
    for (int nt = 0; nt < 3; nt++) {
        const int q0 = nt * 8 + tig * 2, q1 = q0 + 1;
        float e0 = 0.f, e1 = 0.f, e2 = 0.f, e3 = 0.f;
        if (q0 < LQ) {
            size_t o = ((size_t)b * LQ + q0) * LK + k0;
            int m0 = u8 ? (int)M8[o + ra] : M32[o + ra];
            int m2 = u8 ? (int)M8[o + rb] : M32[o + rb];
            e0 = m0 ? 0.f : __expf(acc[nt][0] * SCALE_F);
            e2 = m2 ? 0.f : __expf(acc[nt][2] * SCALE_F);
            g_e[o + ra] = e0;
            g_e[o + rb] = e2;
        }
        if (q1 < LQ) {
            size_t o = ((size_t)b * LQ + q1) * LK + k0;
            int m1 = u8 ? (int)M8[o + ra] : M32[o + ra];
            int m3 = u8 ? (int)M8[o + rb] : M32[o + rb];
            e1 = m1 ? 0.f : __expf(acc[nt][1] * SCALE_F);
            e3 = m3 ? 0.f : __expf(acc[nt][3] * SCALE_F);
            g_e[o + ra] = e1;
            g_e[o + rb] = e3;
        }
        float s0 = e0 + e2, s1 = e1 + e3;
#pragma unroll
        for (int m = 4; m <= 16; m <<= 1) {
            s0 += __shfl_xor_sync(0xffffffffu, s0, m);
            s1 += __shfl_xor_sync(0xffffffffu, s1, m);
        }
        if (gid == 0) {
            if (q0 < LQ) red[w * 24 + q0] = s0;
            if (q1 < LQ) red[w * 24 + q1] = s1;
        }
    }
    __syncthreads();
    if (tid < LQ) {
        float l = 0.f;
#pragma unroll
        for (int ww = 0; ww < 8; ww++) l += red[ww * 24 + tid];
        g_lp[b][mt][tid] = l;
    }
}

// ---------------- p2: attn_fc + context (unchanged; at HBM roofline) ----------------
__global__ __launch_bounds__(T2) void p2(const float* __restrict__ V,
                                         const float* __restrict__ W,
                                         float* __restrict__ out) {
    __shared__ float wl[LQ];
    __shared__ float sa[TK2];
    __shared__ int s_last;
    const int tid  = threadIdx.x;
    const int b    = blockIdx.y;
    const int tile = blockIdx.x;
    const int k0   = tile * TK2;

    if (tid < LQ) {
        float l = 0.f;
#pragma unroll
        for (int t = 0; t < NMT; t++) l += g_lp[b][t][tid];
        wl[tid] = W[tid] / l;
    }
    __syncthreads();

    for (int kk = tid; kk < TK2; kk += T2) {
        const int k = k0 + kk;
        float a = 0.f;
#pragma unroll
        for (int q = 0; q < LQ; q++)
            a = fmaf(g_e[((size_t)b*LQ + q)*LK + k], wl[q], a);
        out[(size_t)NB*DD + (size_t)b*LK + k] = a;
        sa[kk] = a;
    }
    __syncthreads();

    const float4* V4 = (const float4*)(V + ((size_t)b*LK + k0)*DD);
    float cx = 0.f, cy = 0.f, cz = 0.f, cw = 0.f;
#pragma unroll 8
    for (int kk = 0; kk < TK2; kk++) {
        float  av = sa[kk];
        float4 v  = V4[(size_t)kk*(DD/4) + tid];
        cx = fmaf(av, v.x, cx);
        cy = fmaf(av, v.y, cy);
        cz = fmaf(av, v.z, cz);
        cw = fmaf(av, v.w, cw);
    }
    ((float4*)g_cp[b][tile])[tid] = make_float4(cx, cy, cz, cw);
    __threadfence();
    __syncthreads();
    if (tid == 0) s_last = (atomicAdd(&g_cnt[b], 1) == NT2 - 1);
    __syncthreads();
    if (s_last) {
        float4 a = make_float4(0.f, 0.f, 0.f, 0.f);
#pragma unroll
        for (int t = 0; t < NT2; t++) {
            float4 v = ((const float4*)g_cp[b][t])[tid];
            a.x += v.x; a.y += v.y; a.z += v.z; a.w += v.w;
        }
        ((float4*)(out + (size_t)b*DD))[tid] = a;
        if (tid == 0) g_cnt[b] = 0;
    }
}

extern "C" void kernel_launch(void* const* d_in, const int* in_sizes, int n_in,
                              void* d_out, int out_size) {
    const float* Q = (const float*)d_in[0];
    const float* K = (const float*)d_in[1];
    const float* V = (const float*)d_in[2];
    const void*  M = d_in[3];
    const float* W = (const float*)d_in[4];
    float* out = (float*)d_out;

    cudaFuncSetAttribute(p1, cudaFuncAttributeMaxDynamicSharedMemorySize, SMEM1_BYTES);

    p1<<<dim3(NMT, NB), T1, SMEM1_BYTES>>>(Q, K, M);
    p2<<<dim3(NT2, NB), T2>>>(V, W, out);
}